// round 1
// baseline (speedup 1.0000x reference)
#include <cuda_runtime.h>
#include <math.h>

// Problem constants (fixed by the reference: D=1024, R=4096)
#define D 1024
#define R 4096
#define TT (D - 1)      // 1023 time steps
#define TCHUNK 64
#define NCHUNKS 16      // 16*64 = 1024 >= 1023

// ---------------- scratch (no allocation allowed) ----------------
__device__ float g_AI[(size_t)D * R];       // 16 MB
__device__ float g_AN[R];
__device__ float g_partial[NCHUNKS * R];

// ---------------- AN[r] = sum_q adj[r,q] * N[q] ----------------
__global__ void an_kernel(const float* __restrict__ adj, const float* __restrict__ N) {
    int warp = (blockIdx.x * blockDim.x + threadIdx.x) >> 5;
    int lane = threadIdx.x & 31;
    const float* row = adj + (size_t)warp * R;
    float s = 0.f;
    #pragma unroll 4
    for (int q = lane; q < R; q += 32) s = fmaf(row[q], N[q], s);
    #pragma unroll
    for (int o = 16; o; o >>= 1) s += __shfl_down_sync(0xffffffffu, s, o);
    if (lane == 0) g_AN[warp] = s;
}

// ---------------- GEMM: AI[t,r] = sum_q I[t,q] * adj[r,q] ----------------
// C = A * B^T, A = I [M=1024,K=4096] row-major, B = adj [N=4096,K=4096] row-major.
#define BM 128
#define BN 128
#define BK 16

__global__ __launch_bounds__(256) void gemm_nt_kernel(
    const float* __restrict__ A,
    const float* __restrict__ B,
    float* __restrict__ C)
{
    __shared__ float As[BK][BM];
    __shared__ float Bs[BK][BN];
    const int K = R;

    int bm = blockIdx.y * BM;
    int bn = blockIdx.x * BN;
    int tid = threadIdx.x;
    int tx = tid & 15;        // 0..15 -> n sub-tile
    int ty = tid >> 4;        // 0..15 -> m sub-tile
    int lrow = tid >> 2;      // 0..63
    int lkg  = (tid & 3) << 2; // 0,4,8,12

    const float* Aptr = A + (size_t)(bm + lrow) * K + lkg;
    const float* Bptr = B + (size_t)(bn + lrow) * K + lkg;

    float acc[8][8];
    #pragma unroll
    for (int i = 0; i < 8; i++)
        #pragma unroll
        for (int j = 0; j < 8; j++) acc[i][j] = 0.f;

    for (int k0 = 0; k0 < K; k0 += BK) {
        #pragma unroll
        for (int i = 0; i < 2; i++) {
            int row = lrow + i * 64;
            float4 va = *(const float4*)(Aptr + k0 + (size_t)i * 64 * K);
            float4 vb = *(const float4*)(Bptr + k0 + (size_t)i * 64 * K);
            As[lkg + 0][row] = va.x; As[lkg + 1][row] = va.y;
            As[lkg + 2][row] = va.z; As[lkg + 3][row] = va.w;
            Bs[lkg + 0][row] = vb.x; Bs[lkg + 1][row] = vb.y;
            Bs[lkg + 2][row] = vb.z; Bs[lkg + 3][row] = vb.w;
        }
        __syncthreads();

        #pragma unroll
        for (int kk = 0; kk < BK; kk++) {
            float a[8], b[8];
            *(float4*)&a[0] = *(const float4*)&As[kk][ty * 8];
            *(float4*)&a[4] = *(const float4*)&As[kk][ty * 8 + 4];
            *(float4*)&b[0] = *(const float4*)&Bs[kk][tx * 8];
            *(float4*)&b[4] = *(const float4*)&Bs[kk][tx * 8 + 4];
            #pragma unroll
            for (int i = 0; i < 8; i++)
                #pragma unroll
                for (int j = 0; j < 8; j++)
                    acc[i][j] = fmaf(a[i], b[j], acc[i][j]);
        }
        __syncthreads();
    }

    #pragma unroll
    for (int i = 0; i < 8; i++) {
        int m = bm + ty * 8 + i;
        float* Crow = C + (size_t)m * R + bn + tx * 8;
        *(float4*)Crow       = *(float4*)&acc[i][0];
        *(float4*)(Crow + 4) = *(float4*)&acc[i][4];
    }
}

// ---------------- log-prob helpers (analytic Cholesky) ----------------
#define LOG2PI 1.8378770664093454836f

__device__ __forceinline__ float lp1(float n, float p, float x) {
    float m   = n * p;
    float cov = m * (1.f - p);
    float d   = x - m;
    return -0.5f * (LOG2PI + logf(cov) + d * d / cov);
}

__device__ __forceinline__ float lp2(float n, float p1, float p2, float x1, float x2) {
    float m1 = n * p1, m2 = n * p2;
    float d1 = x1 - m1, d2 = x2 - m2;
    float c11 = m1 * (1.f - p1);
    float c22 = m2 * (1.f - p2);
    float c12 = -(m1 * p2);                     // -n p1 p2
    float det = n * m1 * p2 * (1.f - p1 - p2);  // n^2 p1 p2 (1-p1-p2), no cancellation
    float quad = (d1 * d1 * c22 - 2.f * d1 * d2 * c12 + d2 * d2 * c11) / det;
    return -0.5f * (2.f * LOG2PI + logf(det) + quad);
}

// ---------------- elementwise lp accumulation over t-chunks ----------------
__global__ void elem_kernel(
    const float* __restrict__ S,   const float* __restrict__ E,
    const float* __restrict__ I,   const float* __restrict__ T,
    const float* __restrict__ S_E, const float* __restrict__ E_I,
    const float* __restrict__ I_T, const float* __restrict__ I_U,
    const float* __restrict__ T_R, const float* __restrict__ T_D,
    const float* __restrict__ detr, const float* __restrict__ recr,
    const float* __restrict__ cont,
    const float* __restrict__ pdE, const float* __restrict__ pdI,
    const float* __restrict__ pdT)
{
    int r  = blockIdx.x * blockDim.x + threadIdx.x;
    int t0 = blockIdx.y * TCHUNK;
    int t1 = t0 + TCHUNK; if (t1 > TT) t1 = TT;

    float an = g_AN[r];
    float inv_an = 1.f / an;
    float dE = 1.f / (1.f + expf(-pdE[0]));
    float dI = 1.f / (1.f + expf(-pdI[0]));
    float dT = 1.f / (1.f + expf(-pdT[0]));

    float acc = 0.f;
    for (int t = t0; t < t1; t++) {
        size_t idx = (size_t)t * R + r;
        float ai  = g_AI[idx];
        float z   = cont[idx] * ai * inv_an;
        float pSE = -expm1f(-z);

        acc += lp1(S[idx], pSE, S_E[idx]);
        acc += lp1(E[idx], dE,  E_I[idx]);

        float det = detr[idx];
        acc += lp2(I[idx], det * dI, (1.f - det) * dI, I_T[idx], I_U[idx]);

        float rec = recr[idx];
        acc += lp2(T[idx], rec * dT, (1.f - rec) * dT, T_R[idx], T_D[idx]);
    }
    g_partial[blockIdx.y * R + r] = acc;
}

// ---------------- final deterministic reduce over chunks ----------------
__global__ void reduce_kernel(float* __restrict__ out) {
    int r = blockIdx.x * blockDim.x + threadIdx.x;
    float s = 0.f;
    #pragma unroll
    for (int c = 0; c < NCHUNKS; c++) s += g_partial[c * R + r];
    out[r] = s;
}

// ---------------- launch ----------------
extern "C" void kernel_launch(void* const* d_in, const int* in_sizes, int n_in,
                              void* d_out, int out_size) {
    const float* S    = (const float*)d_in[0];
    const float* E    = (const float*)d_in[1];
    const float* I    = (const float*)d_in[2];
    const float* T    = (const float*)d_in[3];
    const float* N    = (const float*)d_in[4];
    const float* S_E  = (const float*)d_in[5];
    const float* E_I  = (const float*)d_in[6];
    const float* I_T  = (const float*)d_in[7];
    const float* I_U  = (const float*)d_in[8];
    const float* T_R  = (const float*)d_in[9];
    const float* T_D  = (const float*)d_in[10];
    const float* adj  = (const float*)d_in[11];
    const float* ldE  = (const float*)d_in[12];
    const float* ldI  = (const float*)d_in[13];
    const float* ldT  = (const float*)d_in[14];
    const float* detr = (const float*)d_in[15];
    const float* recr = (const float*)d_in[16];
    const float* cont = (const float*)d_in[17];
    float* out = (float*)d_out;

    float* AI;
    cudaGetSymbolAddress((void**)&AI, g_AI);

    // 1) AN = adj @ N   (one warp per row)
    an_kernel<<<R / 8, 256>>>(adj, N);

    // 2) AI = I @ adj^T  (M=1024 incl. padded last row; only t<1023 consumed)
    gemm_nt_kernel<<<dim3(R / BN, D / BM), 256>>>(I, adj, AI);

    // 3) elementwise log-probs, partial sums over 64-step t chunks
    elem_kernel<<<dim3(R / 128, NCHUNKS), 128>>>(
        S, E, I, T, S_E, E_I, I_T, I_U, T_R, T_D,
        detr, recr, cont, ldE, ldI, ldT);

    // 4) deterministic final reduce
    reduce_kernel<<<R / 128, 128>>>(out);
}

// round 3
// speedup vs baseline: 2.2554x; 2.2554x over previous
#include <cuda_runtime.h>
#include <cstdint>
#include <math.h>

// Problem constants (fixed by the reference: D=1024, R=4096)
#define D 1024
#define R 4096
#define TT (D - 1)
#define TCHUNK 64
#define NCHUNKS 16

// ---------------- scratch (no allocation allowed) ----------------
__device__ float g_AI[(size_t)D * R];       // 16 MB
__device__ float g_AN[R];
__device__ float g_partial[NCHUNKS * R];

// ================= PTX helpers (sm_80-class only: no 'a'-gated features) ========
__device__ __forceinline__ uint32_t smem_u32(const void* p) {
    uint32_t a;
    asm("{ .reg .u64 t; cvta.to.shared.u64 t, %1; cvt.u32.u64 %0, t; }" : "=r"(a) : "l"(p));
    return a;
}

#define CPASYNC16(saddr, gaddr) \
    asm volatile("cp.async.cg.shared.global [%0], [%1], 16;" :: "r"(saddr), "l"(gaddr) : "memory")
#define CPASYNC_COMMIT() asm volatile("cp.async.commit_group;" ::: "memory")
#define CPASYNC_WAIT1()  asm volatile("cp.async.wait_group 1;" ::: "memory")

#define LDSM_X4(r0, r1, r2, r3, addr) \
    asm volatile("ldmatrix.sync.aligned.m8n8.x4.shared.b16 {%0,%1,%2,%3}, [%4];" \
                 : "=r"(r0), "=r"(r1), "=r"(r2), "=r"(r3) : "r"(addr))

#define MMA_TF32(c, a0, a1, a2, a3, b0, b1) \
    asm volatile("mma.sync.aligned.m16n8k8.row.col.f32.tf32.tf32.f32 " \
                 "{%0,%1,%2,%3}, {%4,%5,%6,%7}, {%8,%9}, {%0,%1,%2,%3};" \
                 : "+f"((c)[0]), "+f"((c)[1]), "+f"((c)[2]), "+f"((c)[3]) \
                 : "r"(a0), "r"(a1), "r"(a2), "r"(a3), "r"(b0), "r"(b1))

__device__ __forceinline__ uint32_t f2tf(uint32_t x) {
    uint32_t d;
    asm("cvt.rna.tf32.f32 %0, %1;" : "=r"(d) : "f"(__uint_as_float(x)));
    return d;
}

// ================= tf32 mma.sync GEMM: C[m,n] = sum_k A[m,k]*B[n,k] (NT) ========
// A = I [1024 x 4096], B = adj [4096 x 4096], both row-major K-contiguous.
#define BM 128
#define BN 128
#define BK 32
#define NK (R / BK)            // 128 k-chunks
#define NSTG 3
#define A_STG 16384            // 128 rows x 128 B
#define STG   32768            // A + B
#define GEMM_SMEM (NSTG * STG) // 98304 B

__global__ void __launch_bounds__(256) gemm_mma(
    const float* __restrict__ A, const float* __restrict__ B, float* __restrict__ C)
{
    extern __shared__ char smem[];
    const uint32_t sbase = smem_u32(smem);
    const int tid  = threadIdx.x;
    const int lane = tid & 31;
    const int wid  = tid >> 5;
    const int bm = blockIdx.y * BM;
    const int bn = blockIdx.x * BN;

    // ---- producer addressing: thread t loads 4x16B for A and for B per stage ----
    const int prow = tid >> 3;          // 0..31
    const int pc   = tid & 7;           // 16B segment within 128B row
    const float* gA = A + (size_t)(bm + prow) * R + pc * 4;
    const float* gB = B + (size_t)(bn + prow) * R + pc * 4;
    const uint32_t so = (uint32_t)prow * 128 + ((uint32_t)((pc ^ (prow & 7))) << 4);

#define ISSUE_STAGE(kt, s)                                              \
    do {                                                                \
        uint32_t dA = sbase + (s) * STG + so;                           \
        uint32_t dB = dA + A_STG;                                       \
        const float* pa = gA + (kt) * BK;                               \
        const float* pb = gB + (kt) * BK;                               \
        _Pragma("unroll")                                               \
        for (int i = 0; i < 4; i++) {                                   \
            CPASYNC16(dA + 4096u * i, pa + (size_t)32 * i * R);         \
            CPASYNC16(dB + 4096u * i, pb + (size_t)32 * i * R);         \
        }                                                               \
    } while (0)

    // ---- consumer addressing ----
    const int wm = (wid & 3) * 32;      // 4 warps along M
    const int wn = (wid >> 2) * 64;     // 2 warps along N
    const int mat = lane >> 3;          // ldmatrix submatrix id
    const int mr  = lane & 7;           // row within submatrix
    const int mhi = mat >> 1;           // k-half
    const int mlo = mat & 1;            // row-block

    uint32_t aoff[2], boff[4];
    #pragma unroll
    for (int fm = 0; fm < 2; fm++) aoff[fm] = (uint32_t)(wm + fm * 16 + mlo * 8 + mr) * 128;
    #pragma unroll
    for (int nb = 0; nb < 4; nb++)  boff[nb] = (uint32_t)(wn + nb * 16 + mlo * 8 + mr) * 128 + A_STG;

    float c[2][8][4];
    #pragma unroll
    for (int fm = 0; fm < 2; fm++)
        #pragma unroll
        for (int nf = 0; nf < 8; nf++)
            #pragma unroll
            for (int v = 0; v < 4; v++) c[fm][nf][v] = 0.f;

    // ---- prologue: fill stages 0,1 ----
    ISSUE_STAGE(0, 0); CPASYNC_COMMIT();
    ISSUE_STAGE(1, 1); CPASYNC_COMMIT();

    // ---- main loop ----
    for (int kt = 0; kt < NK; kt++) {
        const int s = kt % NSTG;
        CPASYNC_WAIT1();
        __syncthreads();

        if (kt + 2 < NK) { ISSUE_STAGE(kt + 2, (kt + 2) % NSTG); }
        CPASYNC_COMMIT();

        const uint32_t st = sbase + s * STG;
        #pragma unroll
        for (int kk = 0; kk < 4; kk++) {
            const uint32_t sw = (uint32_t)(((kk * 2 + mhi) ^ mr)) << 4;

            uint32_t a[2][4], bq[4][4];
            #pragma unroll
            for (int fm = 0; fm < 2; fm++)
                LDSM_X4(a[fm][0], a[fm][1], a[fm][2], a[fm][3], st + aoff[fm] + sw);
            #pragma unroll
            for (int nb = 0; nb < 4; nb++)
                LDSM_X4(bq[nb][0], bq[nb][1], bq[nb][2], bq[nb][3], st + boff[nb] + sw);

            #pragma unroll
            for (int fm = 0; fm < 2; fm++)
                #pragma unroll
                for (int v = 0; v < 4; v++) a[fm][v] = f2tf(a[fm][v]);
            #pragma unroll
            for (int nb = 0; nb < 4; nb++)
                #pragma unroll
                for (int v = 0; v < 4; v++) bq[nb][v] = f2tf(bq[nb][v]);

            #pragma unroll
            for (int fm = 0; fm < 2; fm++)
                #pragma unroll
                for (int nf = 0; nf < 8; nf++) {
                    const int nb = nf >> 1, od = nf & 1;
                    MMA_TF32(c[fm][nf], a[fm][0], a[fm][1], a[fm][2], a[fm][3],
                             bq[nb][od], bq[nb][od + 2]);
                }
        }
        __syncthreads();
    }

    // ---- epilogue ----
    const int g  = lane >> 2;
    const int t2 = (lane & 3) * 2;
    #pragma unroll
    for (int fm = 0; fm < 2; fm++) {
        float* p0 = C + (size_t)(bm + wm + fm * 16 + g) * R + bn + wn + t2;
        #pragma unroll
        for (int nf = 0; nf < 8; nf++) {
            *(float2*)(p0 + nf * 8)            = make_float2(c[fm][nf][0], c[fm][nf][1]);
            *(float2*)(p0 + 8 * R + nf * 8)    = make_float2(c[fm][nf][2], c[fm][nf][3]);
        }
    }
#undef ISSUE_STAGE
}

// ---------------- AN[r] = sum_q adj[r,q] * N[q] ----------------
__global__ void an_kernel(const float* __restrict__ adj, const float* __restrict__ N) {
    int warp = (blockIdx.x * blockDim.x + threadIdx.x) >> 5;
    int lane = threadIdx.x & 31;
    const float* row = adj + (size_t)warp * R;
    float s = 0.f;
    #pragma unroll 4
    for (int q = lane; q < R; q += 32) s = fmaf(row[q], N[q], s);
    #pragma unroll
    for (int o = 16; o; o >>= 1) s += __shfl_down_sync(0xffffffffu, s, o);
    if (lane == 0) g_AN[warp] = s;
}

// ---------------- log-prob helpers (analytic Cholesky) ----------------
#define LOG2PI 1.8378770664093454836f

__device__ __forceinline__ float lp1(float n, float p, float x) {
    float m   = n * p;
    float cov = m * (1.f - p);
    float d   = x - m;
    return -0.5f * (LOG2PI + logf(cov) + d * d / cov);
}

__device__ __forceinline__ float lp2(float n, float p1, float p2, float x1, float x2) {
    float m1 = n * p1, m2 = n * p2;
    float d1 = x1 - m1, d2 = x2 - m2;
    float c11 = m1 * (1.f - p1);
    float c22 = m2 * (1.f - p2);
    float c12 = -(m1 * p2);
    float det = n * m1 * p2 * (1.f - p1 - p2);
    float quad = (d1 * d1 * c22 - 2.f * d1 * d2 * c12 + d2 * d2 * c11) / det;
    return -0.5f * (2.f * LOG2PI + logf(det) + quad);
}

// ---------------- elementwise lp accumulation over t-chunks ----------------
__global__ void elem_kernel(
    const float* __restrict__ S,   const float* __restrict__ E,
    const float* __restrict__ I,   const float* __restrict__ T,
    const float* __restrict__ S_E, const float* __restrict__ E_I,
    const float* __restrict__ I_T, const float* __restrict__ I_U,
    const float* __restrict__ T_R, const float* __restrict__ T_D,
    const float* __restrict__ detr, const float* __restrict__ recr,
    const float* __restrict__ cont,
    const float* __restrict__ pdE, const float* __restrict__ pdI,
    const float* __restrict__ pdT)
{
    int r  = blockIdx.x * blockDim.x + threadIdx.x;
    int t0 = blockIdx.y * TCHUNK;
    int t1 = t0 + TCHUNK; if (t1 > TT) t1 = TT;

    float inv_an = 1.f / g_AN[r];
    float dE = 1.f / (1.f + expf(-pdE[0]));
    float dI = 1.f / (1.f + expf(-pdI[0]));
    float dT = 1.f / (1.f + expf(-pdT[0]));

    float acc = 0.f;
    for (int t = t0; t < t1; t++) {
        size_t idx = (size_t)t * R + r;
        float ai  = g_AI[idx];
        float z   = cont[idx] * ai * inv_an;
        float pSE = -expm1f(-z);

        acc += lp1(S[idx], pSE, S_E[idx]);
        acc += lp1(E[idx], dE,  E_I[idx]);

        float det = detr[idx];
        acc += lp2(I[idx], det * dI, (1.f - det) * dI, I_T[idx], I_U[idx]);

        float rec = recr[idx];
        acc += lp2(T[idx], rec * dT, (1.f - rec) * dT, T_R[idx], T_D[idx]);
    }
    g_partial[blockIdx.y * R + r] = acc;
}

// ---------------- final deterministic reduce over chunks ----------------
__global__ void reduce_kernel(float* __restrict__ out) {
    int r = blockIdx.x * blockDim.x + threadIdx.x;
    float s = 0.f;
    #pragma unroll
    for (int c = 0; c < NCHUNKS; c++) s += g_partial[c * R + r];
    out[r] = s;
}

// ---------------- launch ----------------
extern "C" void kernel_launch(void* const* d_in, const int* in_sizes, int n_in,
                              void* d_out, int out_size) {
    const float* S    = (const float*)d_in[0];
    const float* E    = (const float*)d_in[1];
    const float* I    = (const float*)d_in[2];
    const float* T    = (const float*)d_in[3];
    const float* N    = (const float*)d_in[4];
    const float* S_E  = (const float*)d_in[5];
    const float* E_I  = (const float*)d_in[6];
    const float* I_T  = (const float*)d_in[7];
    const float* I_U  = (const float*)d_in[8];
    const float* T_R  = (const float*)d_in[9];
    const float* T_D  = (const float*)d_in[10];
    const float* adj  = (const float*)d_in[11];
    const float* ldE  = (const float*)d_in[12];
    const float* ldI  = (const float*)d_in[13];
    const float* ldT  = (const float*)d_in[14];
    const float* detr = (const float*)d_in[15];
    const float* recr = (const float*)d_in[16];
    const float* cont = (const float*)d_in[17];
    float* out = (float*)d_out;

    float* AI;
    cudaGetSymbolAddress((void**)&AI, g_AI);

    cudaFuncSetAttribute(gemm_mma, cudaFuncAttributeMaxDynamicSharedMemorySize, GEMM_SMEM);

    // 1) AN = adj @ N
    an_kernel<<<R / 8, 256>>>(adj, N);

    // 2) AI = I @ adj^T via mma.sync tf32 (row 1023 computed but unused)
    gemm_mma<<<dim3(R / BN, D / BM), 256, GEMM_SMEM>>>(I, adj, AI);

    // 3) elementwise log-probs, partial sums over 64-step t chunks
    elem_kernel<<<dim3(R / 128, NCHUNKS), 128>>>(
        S, E, I, T, S_E, E_I, I_T, I_U, T_R, T_D,
        detr, recr, cont, ldE, ldI, ldT);

    // 4) deterministic final reduce
    reduce_kernel<<<R / 128, 128>>>(out);
}

// round 4
// speedup vs baseline: 2.8691x; 1.2721x over previous
#include <cuda_runtime.h>
#include <cuda_bf16.h>
#include <cstdint>
#include <math.h>

// Problem constants (fixed by the reference: D=1024, R=4096)
#define D 1024
#define R 4096
#define TT (D - 1)
#define TCHUNK 64
#define NCHUNKS 16

// ---------------- scratch (no allocation allowed) ----------------
__device__ float g_AI[(size_t)D * R];                 // 16 MB
__device__ float g_AN[R];
__device__ float g_partial[NCHUNKS * R];
__device__ __nv_bfloat16 g_Ib[(size_t)D * R];         // 8 MB
__device__ __nv_bfloat16 g_ADJb[(size_t)R * R];       // 32 MB

// ================= PTX helpers (sm_80-class only) =================
__device__ __forceinline__ uint32_t smem_u32(const void* p) {
    uint32_t a;
    asm("{ .reg .u64 t; cvta.to.shared.u64 t, %1; cvt.u32.u64 %0, t; }" : "=r"(a) : "l"(p));
    return a;
}

#define CPASYNC16(saddr, gaddr) \
    asm volatile("cp.async.cg.shared.global [%0], [%1], 16;" :: "r"(saddr), "l"(gaddr) : "memory")
#define CPASYNC_COMMIT() asm volatile("cp.async.commit_group;" ::: "memory")
#define CPASYNC_WAIT1()  asm volatile("cp.async.wait_group 1;" ::: "memory")

#define LDSM_X4(r0, r1, r2, r3, addr) \
    asm volatile("ldmatrix.sync.aligned.m8n8.x4.shared.b16 {%0,%1,%2,%3}, [%4];" \
                 : "=r"(r0), "=r"(r1), "=r"(r2), "=r"(r3) : "r"(addr))

#define MMA_BF16(c, a0, a1, a2, a3, b0, b1) \
    asm volatile("mma.sync.aligned.m16n8k16.row.col.f32.bf16.bf16.f32 " \
                 "{%0,%1,%2,%3}, {%4,%5,%6,%7}, {%8,%9}, {%0,%1,%2,%3};" \
                 : "+f"((c)[0]), "+f"((c)[1]), "+f"((c)[2]), "+f"((c)[3]) \
                 : "r"(a0), "r"(a1), "r"(a2), "r"(a3), "r"(b0), "r"(b1))

// ---------------- f32 -> bf16 conversion prepass ----------------
__global__ void cvt_kernel(const float* __restrict__ src, __nv_bfloat16* __restrict__ dst,
                           int n8) {
    int i = blockIdx.x * blockDim.x + threadIdx.x;
    int stride = gridDim.x * blockDim.x;
    for (; i < n8; i += stride) {
        float4 v0 = ((const float4*)src)[2 * i];
        float4 v1 = ((const float4*)src)[2 * i + 1];
        __nv_bfloat162 b0 = __floats2bfloat162_rn(v0.x, v0.y);
        __nv_bfloat162 b1 = __floats2bfloat162_rn(v0.z, v0.w);
        __nv_bfloat162 b2 = __floats2bfloat162_rn(v1.x, v1.y);
        __nv_bfloat162 b3 = __floats2bfloat162_rn(v1.z, v1.w);
        uint4 o;
        o.x = *(uint32_t*)&b0; o.y = *(uint32_t*)&b1;
        o.z = *(uint32_t*)&b2; o.w = *(uint32_t*)&b3;
        ((uint4*)dst)[i] = o;
    }
}

// ================= bf16 mma.sync GEMM: C[m,n] = sum_k A[m,k]*B[n,k] (NT) ========
// A = I_bf16 [1024 x 4096], B = adj_bf16 [4096 x 4096], row-major K-contiguous.
#define BM 128
#define BN 128
#define BK 64                   // bf16 elements per chunk: 128 B per row
#define NKC (R / BK)            // 64 k-chunks
#define A_STG 16384             // 128 rows x 128 B
#define STG   32768             // A + B
#define GEMM_SMEM (3 * STG)     // 98304 B

__global__ void __launch_bounds__(256) gemm_mma(
    const __nv_bfloat16* __restrict__ A, const __nv_bfloat16* __restrict__ B,
    float* __restrict__ C)
{
    extern __shared__ char smem[];
    const uint32_t sbase = smem_u32(smem);
    const int tid  = threadIdx.x;
    const int lane = tid & 31;
    const int wid  = tid >> 5;
    const int bm = blockIdx.y * BM;
    const int bn = blockIdx.x * BN;

    // ---- producer addressing: thread t loads 4x16B for A and for B per stage ----
    const int prow = tid >> 3;          // 0..31
    const int pc   = tid & 7;           // 16B segment within 128B row
    const __nv_bfloat16* gA = A + (size_t)(bm + prow) * R + pc * 8;
    const __nv_bfloat16* gB = B + (size_t)(bn + prow) * R + pc * 8;
    const uint32_t so = (uint32_t)prow * 128 + ((uint32_t)((pc ^ (prow & 7))) << 4);

#define ISSUE_STAGE(kt, s)                                              \
    do {                                                                \
        uint32_t dA = sbase + (s) * STG + so;                           \
        uint32_t dB = dA + A_STG;                                       \
        const __nv_bfloat16* pa = gA + (kt) * BK;                       \
        const __nv_bfloat16* pb = gB + (kt) * BK;                       \
        _Pragma("unroll")                                               \
        for (int i = 0; i < 4; i++) {                                   \
            CPASYNC16(dA + 4096u * i, pa + (size_t)32 * i * R);         \
            CPASYNC16(dB + 4096u * i, pb + (size_t)32 * i * R);         \
        }                                                               \
    } while (0)

    // ---- consumer addressing ----
    const int wm = (wid & 3) * 32;      // 4 warps along M
    const int wn = (wid >> 2) * 64;     // 2 warps along N
    const int l15 = lane & 15;
    const int lhi = lane >> 4;          // k-half chunk select
    const int l7  = lane & 7;           // swizzle row bits

    uint32_t aoff[2], boff[4];
    #pragma unroll
    for (int fm = 0; fm < 2; fm++) aoff[fm] = (uint32_t)(wm + fm * 16 + l15) * 128;
    #pragma unroll
    for (int nb = 0; nb < 4; nb++)  boff[nb] = (uint32_t)(wn + nb * 16 + l15) * 128 + A_STG;

    float c[2][8][4];
    #pragma unroll
    for (int fm = 0; fm < 2; fm++)
        #pragma unroll
        for (int nf = 0; nf < 8; nf++)
            #pragma unroll
            for (int v = 0; v < 4; v++) c[fm][nf][v] = 0.f;

    // ---- prologue: fill stages 0,1 ----
    ISSUE_STAGE(0, 0); CPASYNC_COMMIT();
    ISSUE_STAGE(1, 1); CPASYNC_COMMIT();

    // ---- main loop over 64 K-chunks of 64 ----
    for (int kt = 0; kt < NKC; kt++) {
        const int s = kt % 3;
        CPASYNC_WAIT1();
        __syncthreads();

        if (kt + 2 < NKC) { ISSUE_STAGE(kt + 2, (kt + 2) % 3); }
        CPASYNC_COMMIT();

        const uint32_t st = sbase + s * STG;
        #pragma unroll
        for (int kk = 0; kk < 4; kk++) {   // 4 x k16 per chunk
            const uint32_t sw = (uint32_t)(((kk * 2 + lhi) ^ l7)) << 4;

            uint32_t a[2][4], bq[4][4];
            #pragma unroll
            for (int fm = 0; fm < 2; fm++)
                LDSM_X4(a[fm][0], a[fm][1], a[fm][2], a[fm][3], st + aoff[fm] + sw);
            #pragma unroll
            for (int nb = 0; nb < 4; nb++)
                LDSM_X4(bq[nb][0], bq[nb][1], bq[nb][2], bq[nb][3], st + boff[nb] + sw);

            #pragma unroll
            for (int fm = 0; fm < 2; fm++)
                #pragma unroll
                for (int nf = 0; nf < 8; nf++) {
                    const int nb = nf >> 1, od = nf & 1;
                    MMA_BF16(c[fm][nf], a[fm][0], a[fm][1], a[fm][2], a[fm][3],
                             bq[nb][od], bq[nb][od + 2]);
                }
        }
        __syncthreads();
    }

    // ---- epilogue ----
    const int g  = lane >> 2;
    const int t2 = (lane & 3) * 2;
    #pragma unroll
    for (int fm = 0; fm < 2; fm++) {
        float* p0 = C + (size_t)(bm + wm + fm * 16 + g) * R + bn + wn + t2;
        #pragma unroll
        for (int nf = 0; nf < 8; nf++) {
            *(float2*)(p0 + nf * 8)         = make_float2(c[fm][nf][0], c[fm][nf][1]);
            *(float2*)(p0 + 8 * R + nf * 8) = make_float2(c[fm][nf][2], c[fm][nf][3]);
        }
    }
#undef ISSUE_STAGE
}

// ---------------- AN[r] = sum_q adj[r,q] * N[q] ----------------
__global__ void an_kernel(const float* __restrict__ adj, const float* __restrict__ N) {
    int warp = (blockIdx.x * blockDim.x + threadIdx.x) >> 5;
    int lane = threadIdx.x & 31;
    const float* row = adj + (size_t)warp * R;
    float s = 0.f;
    #pragma unroll 4
    for (int q = lane; q < R; q += 32) s = fmaf(row[q], N[q], s);
    #pragma unroll
    for (int o = 16; o; o >>= 1) s += __shfl_down_sync(0xffffffffu, s, o);
    if (lane == 0) g_AN[warp] = s;
}

// ---------------- log-prob helpers (analytic Cholesky) ----------------
#define LOG2PI 1.8378770664093454836f

__device__ __forceinline__ float lp1(float n, float p, float x) {
    float m   = n * p;
    float cov = m * (1.f - p);
    float d   = x - m;
    return -0.5f * (LOG2PI + logf(cov) + d * d / cov);
}

__device__ __forceinline__ float lp2(float n, float p1, float p2, float x1, float x2) {
    float m1 = n * p1, m2 = n * p2;
    float d1 = x1 - m1, d2 = x2 - m2;
    float c11 = m1 * (1.f - p1);
    float c22 = m2 * (1.f - p2);
    float c12 = -(m1 * p2);
    float det = n * m1 * p2 * (1.f - p1 - p2);
    float quad = (d1 * d1 * c22 - 2.f * d1 * d2 * c12 + d2 * d2 * c11) / det;
    return -0.5f * (2.f * LOG2PI + logf(det) + quad);
}

// ---------------- elementwise lp accumulation over t-chunks ----------------
__global__ void elem_kernel(
    const float* __restrict__ S,   const float* __restrict__ E,
    const float* __restrict__ I,   const float* __restrict__ T,
    const float* __restrict__ S_E, const float* __restrict__ E_I,
    const float* __restrict__ I_T, const float* __restrict__ I_U,
    const float* __restrict__ T_R, const float* __restrict__ T_D,
    const float* __restrict__ detr, const float* __restrict__ recr,
    const float* __restrict__ cont,
    const float* __restrict__ pdE, const float* __restrict__ pdI,
    const float* __restrict__ pdT)
{
    int r  = blockIdx.x * blockDim.x + threadIdx.x;
    int t0 = blockIdx.y * TCHUNK;
    int t1 = t0 + TCHUNK; if (t1 > TT) t1 = TT;

    float inv_an = 1.f / g_AN[r];
    float dE = 1.f / (1.f + expf(-pdE[0]));
    float dI = 1.f / (1.f + expf(-pdI[0]));
    float dT = 1.f / (1.f + expf(-pdT[0]));

    float acc = 0.f;
    for (int t = t0; t < t1; t++) {
        size_t idx = (size_t)t * R + r;
        float ai  = g_AI[idx];
        float z   = cont[idx] * ai * inv_an;
        float pSE = -expm1f(-z);

        acc += lp1(S[idx], pSE, S_E[idx]);
        acc += lp1(E[idx], dE,  E_I[idx]);

        float det = detr[idx];
        acc += lp2(I[idx], det * dI, (1.f - det) * dI, I_T[idx], I_U[idx]);

        float rec = recr[idx];
        acc += lp2(T[idx], rec * dT, (1.f - rec) * dT, T_R[idx], T_D[idx]);
    }
    g_partial[blockIdx.y * R + r] = acc;
}

// ---------------- final deterministic reduce over chunks ----------------
__global__ void reduce_kernel(float* __restrict__ out) {
    int r = blockIdx.x * blockDim.x + threadIdx.x;
    float s = 0.f;
    #pragma unroll
    for (int c = 0; c < NCHUNKS; c++) s += g_partial[c * R + r];
    out[r] = s;
}

// ---------------- launch ----------------
extern "C" void kernel_launch(void* const* d_in, const int* in_sizes, int n_in,
                              void* d_out, int out_size) {
    const float* S    = (const float*)d_in[0];
    const float* E    = (const float*)d_in[1];
    const float* I    = (const float*)d_in[2];
    const float* T    = (const float*)d_in[3];
    const float* N    = (const float*)d_in[4];
    const float* S_E  = (const float*)d_in[5];
    const float* E_I  = (const float*)d_in[6];
    const float* I_T  = (const float*)d_in[7];
    const float* I_U  = (const float*)d_in[8];
    const float* T_R  = (const float*)d_in[9];
    const float* T_D  = (const float*)d_in[10];
    const float* adj  = (const float*)d_in[11];
    const float* ldE  = (const float*)d_in[12];
    const float* ldI  = (const float*)d_in[13];
    const float* ldT  = (const float*)d_in[14];
    const float* detr = (const float*)d_in[15];
    const float* recr = (const float*)d_in[16];
    const float* cont = (const float*)d_in[17];
    float* out = (float*)d_out;

    float* AI;             cudaGetSymbolAddress((void**)&AI, g_AI);
    __nv_bfloat16* Ib;     cudaGetSymbolAddress((void**)&Ib, g_Ib);
    __nv_bfloat16* ADJb;   cudaGetSymbolAddress((void**)&ADJb, g_ADJb);

    cudaFuncSetAttribute(gemm_mma, cudaFuncAttributeMaxDynamicSharedMemorySize, GEMM_SMEM);

    // 0) bf16 conversion prepass
    cvt_kernel<<<2048, 256>>>(adj, ADJb, (int)((size_t)R * R / 8));
    cvt_kernel<<<1024, 256>>>(I, Ib, (int)((size_t)D * R / 8));

    // 1) AN = adj @ N
    an_kernel<<<R / 8, 256>>>(adj, N);

    // 2) AI = I @ adj^T via mma.sync bf16 (row 1023 computed but unused)
    gemm_mma<<<dim3(R / BN, D / BM), 256, GEMM_SMEM>>>(Ib, ADJb, AI);

    // 3) elementwise log-probs, partial sums over 64-step t chunks
    elem_kernel<<<dim3(R / 128, NCHUNKS), 128>>>(
        S, E, I, T, S_E, E_I, I_T, I_U, T_R, T_D,
        detr, recr, cont, ldE, ldI, ldT);

    // 4) deterministic final reduce
    reduce_kernel<<<R / 128, 128>>>(out);
}

// round 5
// speedup vs baseline: 6.2094x; 2.1642x over previous
#include <cuda_runtime.h>
#include <cuda_bf16.h>
#include <cstdint>
#include <math.h>

// Problem constants (fixed by the reference: D=1024, R=4096)
#define D 1024
#define R 4096
#define TT (D - 1)
#define TCHUNK 16
#define NCHUNKS 64              // 64*16 = 1024 >= 1023

// ---------------- scratch (no allocation allowed) ----------------
__device__ float g_AI[(size_t)D * R];                 // 16 MB
__device__ float g_AN[R];
__device__ float g_partial[NCHUNKS * R];              // 1 MB
__device__ __nv_bfloat16 g_Ib[(size_t)D * R];         // 8 MB
__device__ __nv_bfloat16 g_ADJb[(size_t)R * R];       // 32 MB

// ================= PTX helpers (sm_80-class only) =================
__device__ __forceinline__ uint32_t smem_u32(const void* p) {
    uint32_t a;
    asm("{ .reg .u64 t; cvta.to.shared.u64 t, %1; cvt.u32.u64 %0, t; }" : "=r"(a) : "l"(p));
    return a;
}

#define CPASYNC16(saddr, gaddr) \
    asm volatile("cp.async.cg.shared.global [%0], [%1], 16;" :: "r"(saddr), "l"(gaddr) : "memory")
#define CPASYNC_COMMIT() asm volatile("cp.async.commit_group;" ::: "memory")
#define CPASYNC_WAIT2()  asm volatile("cp.async.wait_group 2;" ::: "memory")

#define LDSM_X4(r0, r1, r2, r3, addr) \
    asm volatile("ldmatrix.sync.aligned.m8n8.x4.shared.b16 {%0,%1,%2,%3}, [%4];" \
                 : "=r"(r0), "=r"(r1), "=r"(r2), "=r"(r3) : "r"(addr))

#define MMA_BF16(c, a0, a1, a2, a3, b0, b1) \
    asm volatile("mma.sync.aligned.m16n8k16.row.col.f32.bf16.bf16.f32 " \
                 "{%0,%1,%2,%3}, {%4,%5,%6,%7}, {%8,%9}, {%0,%1,%2,%3};" \
                 : "+f"((c)[0]), "+f"((c)[1]), "+f"((c)[2]), "+f"((c)[3]) \
                 : "r"(a0), "r"(a1), "r"(a2), "r"(a3), "r"(b0), "r"(b1))

// ---------------- fused adj: f32->bf16 convert + AN[r] = adj[r,:] . N ----------
__global__ void __launch_bounds__(128) cvt_adj_an(
    const float* __restrict__ adj, const float* __restrict__ Nv,
    __nv_bfloat16* __restrict__ dst)
{
    __shared__ float wsum[4];
    const int r = blockIdx.x;
    const float* row = adj + (size_t)r * R;
    __nv_bfloat16* orow = dst + (size_t)r * R;

    float s = 0.f;
    #pragma unroll
    for (int it = 0; it < R / (128 * 8); it++) {
        int q = (it * 128 + threadIdx.x) * 8;
        float4 a = *(const float4*)(row + q);
        float4 b = *(const float4*)(row + q + 4);
        float4 n0 = *(const float4*)(Nv + q);
        float4 n1 = *(const float4*)(Nv + q + 4);
        __nv_bfloat162 c0 = __floats2bfloat162_rn(a.x, a.y);
        __nv_bfloat162 c1 = __floats2bfloat162_rn(a.z, a.w);
        __nv_bfloat162 c2 = __floats2bfloat162_rn(b.x, b.y);
        __nv_bfloat162 c3 = __floats2bfloat162_rn(b.z, b.w);
        uint4 o;
        o.x = *(uint32_t*)&c0; o.y = *(uint32_t*)&c1;
        o.z = *(uint32_t*)&c2; o.w = *(uint32_t*)&c3;
        *(uint4*)(orow + q) = o;
        s = fmaf(a.x, n0.x, s); s = fmaf(a.y, n0.y, s);
        s = fmaf(a.z, n0.z, s); s = fmaf(a.w, n0.w, s);
        s = fmaf(b.x, n1.x, s); s = fmaf(b.y, n1.y, s);
        s = fmaf(b.z, n1.z, s); s = fmaf(b.w, n1.w, s);
    }
    #pragma unroll
    for (int o = 16; o; o >>= 1) s += __shfl_down_sync(0xffffffffu, s, o);
    int lane = threadIdx.x & 31, wid = threadIdx.x >> 5;
    if (lane == 0) wsum[wid] = s;
    __syncthreads();
    if (threadIdx.x == 0)
        g_AN[r] = wsum[0] + wsum[1] + wsum[2] + wsum[3];
}

// ---------------- f32 -> bf16 conversion (I matrix) ----------------
__global__ void cvt_kernel(const float* __restrict__ src, __nv_bfloat16* __restrict__ dst,
                           int n8) {
    int i = blockIdx.x * blockDim.x + threadIdx.x;
    int stride = gridDim.x * blockDim.x;
    for (; i < n8; i += stride) {
        float4 v0 = ((const float4*)src)[2 * i];
        float4 v1 = ((const float4*)src)[2 * i + 1];
        __nv_bfloat162 b0 = __floats2bfloat162_rn(v0.x, v0.y);
        __nv_bfloat162 b1 = __floats2bfloat162_rn(v0.z, v0.w);
        __nv_bfloat162 b2 = __floats2bfloat162_rn(v1.x, v1.y);
        __nv_bfloat162 b3 = __floats2bfloat162_rn(v1.z, v1.w);
        uint4 o;
        o.x = *(uint32_t*)&b0; o.y = *(uint32_t*)&b1;
        o.z = *(uint32_t*)&b2; o.w = *(uint32_t*)&b3;
        ((uint4*)dst)[i] = o;
    }
}

// ================= bf16 mma.sync GEMM: C[m,n] = sum_k A[m,k]*B[n,k] (NT) ========
#define BM 128
#define BN 128
#define BK 64                   // bf16 elements per chunk: 128 B per row
#define NKC (R / BK)            // 64 k-chunks
#define NSTG 4
#define A_STG 16384             // 128 rows x 128 B
#define STG   32768             // A + B
#define GEMM_SMEM (NSTG * STG)  // 131072 B

__global__ void __launch_bounds__(256) gemm_mma(
    const __nv_bfloat16* __restrict__ A, const __nv_bfloat16* __restrict__ B,
    float* __restrict__ C)
{
    extern __shared__ char smem[];
    const uint32_t sbase = smem_u32(smem);
    const int tid  = threadIdx.x;
    const int lane = tid & 31;
    const int wid  = tid >> 5;
    const int bm = blockIdx.y * BM;
    const int bn = blockIdx.x * BN;

    const int prow = tid >> 3;
    const int pc   = tid & 7;
    const __nv_bfloat16* gA = A + (size_t)(bm + prow) * R + pc * 8;
    const __nv_bfloat16* gB = B + (size_t)(bn + prow) * R + pc * 8;
    const uint32_t so = (uint32_t)prow * 128 + ((uint32_t)((pc ^ (prow & 7))) << 4);

#define ISSUE_STAGE(kt, s)                                              \
    do {                                                                \
        uint32_t dA = sbase + (s) * STG + so;                           \
        uint32_t dB = dA + A_STG;                                       \
        const __nv_bfloat16* pa = gA + (kt) * BK;                       \
        const __nv_bfloat16* pb = gB + (kt) * BK;                       \
        _Pragma("unroll")                                               \
        for (int i = 0; i < 4; i++) {                                   \
            CPASYNC16(dA + 4096u * i, pa + (size_t)32 * i * R);         \
            CPASYNC16(dB + 4096u * i, pb + (size_t)32 * i * R);         \
        }                                                               \
    } while (0)

    const int wm = (wid & 3) * 32;
    const int wn = (wid >> 2) * 64;
    const int l15 = lane & 15;
    const int lhi = lane >> 4;
    const int l7  = lane & 7;

    uint32_t aoff[2], boff[4];
    #pragma unroll
    for (int fm = 0; fm < 2; fm++) aoff[fm] = (uint32_t)(wm + fm * 16 + l15) * 128;
    #pragma unroll
    for (int nb = 0; nb < 4; nb++)  boff[nb] = (uint32_t)(wn + nb * 16 + l15) * 128 + A_STG;

    float c[2][8][4];
    #pragma unroll
    for (int fm = 0; fm < 2; fm++)
        #pragma unroll
        for (int nf = 0; nf < 8; nf++)
            #pragma unroll
            for (int v = 0; v < 4; v++) c[fm][nf][v] = 0.f;

    ISSUE_STAGE(0, 0); CPASYNC_COMMIT();
    ISSUE_STAGE(1, 1); CPASYNC_COMMIT();
    ISSUE_STAGE(2, 2); CPASYNC_COMMIT();

    for (int kt = 0; kt < NKC; kt++) {
        const int s = kt & (NSTG - 1);
        CPASYNC_WAIT2();
        __syncthreads();   // also protects stage (kt+3)%4 == (kt-1)%4 reuse

        if (kt + 3 < NKC) { ISSUE_STAGE(kt + 3, (kt + 3) & (NSTG - 1)); }
        CPASYNC_COMMIT();

        const uint32_t st = sbase + s * STG;
        #pragma unroll
        for (int kk = 0; kk < 4; kk++) {
            const uint32_t sw = (uint32_t)(((kk * 2 + lhi) ^ l7)) << 4;

            uint32_t a[2][4], bq[4][4];
            #pragma unroll
            for (int fm = 0; fm < 2; fm++)
                LDSM_X4(a[fm][0], a[fm][1], a[fm][2], a[fm][3], st + aoff[fm] + sw);
            #pragma unroll
            for (int nb = 0; nb < 4; nb++)
                LDSM_X4(bq[nb][0], bq[nb][1], bq[nb][2], bq[nb][3], st + boff[nb] + sw);

            #pragma unroll
            for (int fm = 0; fm < 2; fm++)
                #pragma unroll
                for (int nf = 0; nf < 8; nf++) {
                    const int nb = nf >> 1, od = nf & 1;
                    MMA_BF16(c[fm][nf], a[fm][0], a[fm][1], a[fm][2], a[fm][3],
                             bq[nb][od], bq[nb][od + 2]);
                }
        }
    }

    const int g  = lane >> 2;
    const int t2 = (lane & 3) * 2;
    #pragma unroll
    for (int fm = 0; fm < 2; fm++) {
        float* p0 = C + (size_t)(bm + wm + fm * 16 + g) * R + bn + wn + t2;
        #pragma unroll
        for (int nf = 0; nf < 8; nf++) {
            *(float2*)(p0 + nf * 8)         = make_float2(c[fm][nf][0], c[fm][nf][1]);
            *(float2*)(p0 + 8 * R + nf * 8) = make_float2(c[fm][nf][2], c[fm][nf][3]);
        }
    }
#undef ISSUE_STAGE
}

// ---------------- elementwise log-prob (fast-math, float4) ----------------
#define LOG2PI 1.8378770664093454836f

__device__ __forceinline__ float lp_all(
    float s, float e, float i, float tt,
    float se, float ei, float it, float iu, float tr, float td,
    float det, float rec, float con, float ai, float inv_an,
    float dE, float dI, float dT)
{
    // S->E (k=1), binomial p from contagion
    float z   = con * ai * inv_an;
    float pSE = 1.f - __expf(-z);            // -expm1(-z)
    float mS  = s * pSE;
    float covS = mS * (1.f - pSE);
    float dS  = se - mS;
    float quadS = __fdividef(dS * dS, covS);

    // E->I (k=1), constant p = dE
    float mE  = e * dE;
    float covE = mE * (1.f - dE);
    float dEe = ei - mE;
    float quadE = __fdividef(dEe * dEe, covE);

    float l1 = __logf(covS * covE);

    // I -> {T, U} (k=2)
    float p1 = det * dI, p2 = (1.f - det) * dI;
    float m1 = i * p1, m2 = i * p2;
    float d1 = it - m1, d2 = iu - m2;
    float c11 = m1 * (1.f - p1);
    float c22 = m2 * (1.f - p2);
    float c12 = -(m1 * p2);
    float detI = i * m1 * p2 * (1.f - p1 - p2);
    float quadI = __fdividef(d1 * d1 * c22 - 2.f * d1 * d2 * c12 + d2 * d2 * c11, detI);

    // T -> {R, D} (k=2)
    float q1 = rec * dT, q2 = (1.f - rec) * dT;
    float n1 = tt * q1, n2 = tt * q2;
    float e1 = tr - n1, e2 = td - n2;
    float b11 = n1 * (1.f - q1);
    float b22 = n2 * (1.f - q2);
    float b12 = -(n1 * q2);
    float detT = tt * n1 * q2 * (1.f - q1 - q2);
    float quadT = __fdividef(e1 * e1 * b22 - 2.f * e1 * e2 * b12 + e2 * e2 * b11, detT);

    float l2 = __logf(detI * detT);

    return -0.5f * (6.f * LOG2PI + l1 + l2 + quadS + quadE + quadI + quadT);
}

__global__ void __launch_bounds__(128) elem_kernel(
    const float* __restrict__ S,   const float* __restrict__ E,
    const float* __restrict__ I,   const float* __restrict__ T,
    const float* __restrict__ S_E, const float* __restrict__ E_I,
    const float* __restrict__ I_T, const float* __restrict__ I_U,
    const float* __restrict__ T_R, const float* __restrict__ T_D,
    const float* __restrict__ detr, const float* __restrict__ recr,
    const float* __restrict__ cont,
    const float* __restrict__ pdE, const float* __restrict__ pdI,
    const float* __restrict__ pdT)
{
    const int r  = (blockIdx.x * blockDim.x + threadIdx.x) * 4;
    const int t0 = blockIdx.y * TCHUNK;
    int t1 = t0 + TCHUNK; if (t1 > TT) t1 = TT;

    float4 an = *(const float4*)&g_AN[r];
    float inv0 = __fdividef(1.f, an.x), inv1 = __fdividef(1.f, an.y);
    float inv2 = __fdividef(1.f, an.z), inv3 = __fdividef(1.f, an.w);
    float dE = __fdividef(1.f, 1.f + __expf(-pdE[0]));
    float dI = __fdividef(1.f, 1.f + __expf(-pdI[0]));
    float dT = __fdividef(1.f, 1.f + __expf(-pdT[0]));

    float a0 = 0.f, a1 = 0.f, a2 = 0.f, a3 = 0.f;
    for (int t = t0; t < t1; t++) {
        size_t idx = (size_t)t * R + r;
        float4 vS  = *(const float4*)(S + idx);
        float4 vE  = *(const float4*)(E + idx);
        float4 vI  = *(const float4*)(I + idx);
        float4 vT  = *(const float4*)(T + idx);
        float4 vse = *(const float4*)(S_E + idx);
        float4 vei = *(const float4*)(E_I + idx);
        float4 vit = *(const float4*)(I_T + idx);
        float4 viu = *(const float4*)(I_U + idx);
        float4 vtr = *(const float4*)(T_R + idx);
        float4 vtd = *(const float4*)(T_D + idx);
        float4 vdt = *(const float4*)(detr + idx);
        float4 vrc = *(const float4*)(recr + idx);
        float4 vcn = *(const float4*)(cont + idx);
        float4 vai = *(const float4*)(g_AI + idx);

        a0 += lp_all(vS.x, vE.x, vI.x, vT.x, vse.x, vei.x, vit.x, viu.x, vtr.x, vtd.x,
                     vdt.x, vrc.x, vcn.x, vai.x, inv0, dE, dI, dT);
        a1 += lp_all(vS.y, vE.y, vI.y, vT.y, vse.y, vei.y, vit.y, viu.y, vtr.y, vtd.y,
                     vdt.y, vrc.y, vcn.y, vai.y, inv1, dE, dI, dT);
        a2 += lp_all(vS.z, vE.z, vI.z, vT.z, vse.z, vei.z, vit.z, viu.z, vtr.z, vtd.z,
                     vdt.z, vrc.z, vcn.z, vai.z, inv2, dE, dI, dT);
        a3 += lp_all(vS.w, vE.w, vI.w, vT.w, vse.w, vei.w, vit.w, viu.w, vtr.w, vtd.w,
                     vdt.w, vrc.w, vcn.w, vai.w, inv3, dE, dI, dT);
    }
    *(float4*)&g_partial[(size_t)blockIdx.y * R + r] = make_float4(a0, a1, a2, a3);
}

// ---------------- final deterministic reduce over chunks ----------------
__global__ void reduce_kernel(float* __restrict__ out) {
    int r = blockIdx.x * blockDim.x + threadIdx.x;
    float s = 0.f;
    #pragma unroll
    for (int c = 0; c < NCHUNKS; c++) s += g_partial[c * R + r];
    out[r] = s;
}

// ---------------- launch ----------------
extern "C" void kernel_launch(void* const* d_in, const int* in_sizes, int n_in,
                              void* d_out, int out_size) {
    const float* S    = (const float*)d_in[0];
    const float* E    = (const float*)d_in[1];
    const float* I    = (const float*)d_in[2];
    const float* T    = (const float*)d_in[3];
    const float* N    = (const float*)d_in[4];
    const float* S_E  = (const float*)d_in[5];
    const float* E_I  = (const float*)d_in[6];
    const float* I_T  = (const float*)d_in[7];
    const float* I_U  = (const float*)d_in[8];
    const float* T_R  = (const float*)d_in[9];
    const float* T_D  = (const float*)d_in[10];
    const float* adj  = (const float*)d_in[11];
    const float* ldE  = (const float*)d_in[12];
    const float* ldI  = (const float*)d_in[13];
    const float* ldT  = (const float*)d_in[14];
    const float* detr = (const float*)d_in[15];
    const float* recr = (const float*)d_in[16];
    const float* cont = (const float*)d_in[17];
    float* out = (float*)d_out;

    float* AI;             cudaGetSymbolAddress((void**)&AI, g_AI);
    __nv_bfloat16* Ib;     cudaGetSymbolAddress((void**)&Ib, g_Ib);
    __nv_bfloat16* ADJb;   cudaGetSymbolAddress((void**)&ADJb, g_ADJb);

    cudaFuncSetAttribute(gemm_mma, cudaFuncAttributeMaxDynamicSharedMemorySize, GEMM_SMEM);

    // 0) fused adj: bf16 convert + AN = adj @ N;  I: bf16 convert
    cvt_adj_an<<<R, 128>>>(adj, N, ADJb);
    cvt_kernel<<<512, 256>>>(I, Ib, (int)((size_t)D * R / 8));

    // 1) AI = I @ adj^T via mma.sync bf16 (row 1023 computed but unused)
    gemm_mma<<<dim3(R / BN, D / BM), 256, GEMM_SMEM>>>(Ib, ADJb, AI);

    // 2) elementwise log-probs (fast-math, float4), partial sums over t chunks
    elem_kernel<<<dim3(R / 512, NCHUNKS), 128>>>(
        S, E, I, T, S_E, E_I, I_T, I_U, T_R, T_D,
        detr, recr, cont, ldE, ldI, ldT);

    // 3) deterministic final reduce
    reduce_kernel<<<R / 128, 128>>>(out);
}

// round 6
// speedup vs baseline: 6.6392x; 1.0692x over previous
#include <cuda_runtime.h>
#include <cuda_bf16.h>
#include <cstdint>
#include <math.h>

// Problem constants (fixed by the reference: D=1024, R=4096)
#define D 1024
#define R 4096
#define TT (D - 1)
#define TCHUNK 8
#define NCHUNKS 128             // 128*8 = 1024 >= 1023

// ---------------- scratch (no allocation allowed) ----------------
__device__ float g_AI[(size_t)D * R];                 // 16 MB
__device__ float g_AN[R];
__device__ float g_partial[NCHUNKS * R];              // 2 MB
__device__ __nv_bfloat16 g_Ib[(size_t)D * R];         // 8 MB
__device__ __nv_bfloat16 g_ADJb[(size_t)R * R];       // 32 MB

// ================= PTX helpers (sm_80-class only) =================
__device__ __forceinline__ uint32_t smem_u32(const void* p) {
    uint32_t a;
    asm("{ .reg .u64 t; cvta.to.shared.u64 t, %1; cvt.u32.u64 %0, t; }" : "=r"(a) : "l"(p));
    return a;
}

#define CPASYNC16(saddr, gaddr) \
    asm volatile("cp.async.cg.shared.global [%0], [%1], 16;" :: "r"(saddr), "l"(gaddr) : "memory")
#define CPASYNC_COMMIT() asm volatile("cp.async.commit_group;" ::: "memory")
#define CPASYNC_WAIT2()  asm volatile("cp.async.wait_group 2;" ::: "memory")

#define LDSM_X4(r0, r1, r2, r3, addr) \
    asm volatile("ldmatrix.sync.aligned.m8n8.x4.shared.b16 {%0,%1,%2,%3}, [%4];" \
                 : "=r"(r0), "=r"(r1), "=r"(r2), "=r"(r3) : "r"(addr))

#define MMA_BF16(c, a0, a1, a2, a3, b0, b1) \
    asm volatile("mma.sync.aligned.m16n8k16.row.col.f32.bf16.bf16.f32 " \
                 "{%0,%1,%2,%3}, {%4,%5,%6,%7}, {%8,%9}, {%0,%1,%2,%3};" \
                 : "+f"((c)[0]), "+f"((c)[1]), "+f"((c)[2]), "+f"((c)[3]) \
                 : "r"(a0), "r"(a1), "r"(a2), "r"(a3), "r"(b0), "r"(b1))

// ---------------- fused adj: f32->bf16 convert + AN[r] = adj[r,:] . N ----------
__global__ void __launch_bounds__(128) cvt_adj_an(
    const float* __restrict__ adj, const float* __restrict__ Nv,
    __nv_bfloat16* __restrict__ dst)
{
    __shared__ float wsum[4];
    const int r = blockIdx.x;
    const float* row = adj + (size_t)r * R;
    __nv_bfloat16* orow = dst + (size_t)r * R;

    float s = 0.f;
    #pragma unroll
    for (int it = 0; it < R / (128 * 8); it++) {
        int q = (it * 128 + threadIdx.x) * 8;
        float4 a = *(const float4*)(row + q);
        float4 b = *(const float4*)(row + q + 4);
        float4 n0 = *(const float4*)(Nv + q);
        float4 n1 = *(const float4*)(Nv + q + 4);
        __nv_bfloat162 c0 = __floats2bfloat162_rn(a.x, a.y);
        __nv_bfloat162 c1 = __floats2bfloat162_rn(a.z, a.w);
        __nv_bfloat162 c2 = __floats2bfloat162_rn(b.x, b.y);
        __nv_bfloat162 c3 = __floats2bfloat162_rn(b.z, b.w);
        uint4 o;
        o.x = *(uint32_t*)&c0; o.y = *(uint32_t*)&c1;
        o.z = *(uint32_t*)&c2; o.w = *(uint32_t*)&c3;
        *(uint4*)(orow + q) = o;
        s = fmaf(a.x, n0.x, s); s = fmaf(a.y, n0.y, s);
        s = fmaf(a.z, n0.z, s); s = fmaf(a.w, n0.w, s);
        s = fmaf(b.x, n1.x, s); s = fmaf(b.y, n1.y, s);
        s = fmaf(b.z, n1.z, s); s = fmaf(b.w, n1.w, s);
    }
    #pragma unroll
    for (int o = 16; o; o >>= 1) s += __shfl_down_sync(0xffffffffu, s, o);
    int lane = threadIdx.x & 31, wid = threadIdx.x >> 5;
    if (lane == 0) wsum[wid] = s;
    __syncthreads();
    if (threadIdx.x == 0)
        g_AN[r] = wsum[0] + wsum[1] + wsum[2] + wsum[3];
}

// ---------------- f32 -> bf16 conversion (I matrix) ----------------
__global__ void cvt_kernel(const float* __restrict__ src, __nv_bfloat16* __restrict__ dst,
                           int n8) {
    int i = blockIdx.x * blockDim.x + threadIdx.x;
    int stride = gridDim.x * blockDim.x;
    for (; i < n8; i += stride) {
        float4 v0 = ((const float4*)src)[2 * i];
        float4 v1 = ((const float4*)src)[2 * i + 1];
        __nv_bfloat162 b0 = __floats2bfloat162_rn(v0.x, v0.y);
        __nv_bfloat162 b1 = __floats2bfloat162_rn(v0.z, v0.w);
        __nv_bfloat162 b2 = __floats2bfloat162_rn(v1.x, v1.y);
        __nv_bfloat162 b3 = __floats2bfloat162_rn(v1.z, v1.w);
        uint4 o;
        o.x = *(uint32_t*)&b0; o.y = *(uint32_t*)&b1;
        o.z = *(uint32_t*)&b2; o.w = *(uint32_t*)&b3;
        ((uint4*)dst)[i] = o;
    }
}

// ================= bf16 mma.sync GEMM: C[m,n] = sum_k A[m,k]*B[n,k] (NT) ========
// 256x128 CTA tile, 8 warps of 64x64 -> grid 32x4 = 128 CTAs = one wave.
#define BM 256
#define BN 128
#define BK 64                   // bf16 elements per chunk: 128 B per row
#define NKC (R / BK)            // 64 k-chunks
#define NSTG 4
#define A_STG 32768             // 256 rows x 128 B
#define B_STG 16384             // 128 rows x 128 B
#define STG   (A_STG + B_STG)   // 49152
#define GEMM_SMEM (NSTG * STG)  // 196608 B

__global__ void __launch_bounds__(256, 1) gemm_mma(
    const __nv_bfloat16* __restrict__ A, const __nv_bfloat16* __restrict__ B,
    float* __restrict__ C)
{
    extern __shared__ char smem[];
    const uint32_t sbase = smem_u32(smem);
    const int tid  = threadIdx.x;
    const int lane = tid & 31;
    const int wid  = tid >> 5;
    const int bm = blockIdx.y * BM;
    const int bn = blockIdx.x * BN;

    // ---- producer addressing: each thread loads 8 A segs + 4 B segs (16B) ----
    const int prow = tid >> 3;          // 0..31
    const int pc   = tid & 7;
    const __nv_bfloat16* gA = A + (size_t)(bm + prow) * R + pc * 8;
    const __nv_bfloat16* gB = B + (size_t)(bn + prow) * R + pc * 8;
    const uint32_t so = (uint32_t)prow * 128 + ((uint32_t)((pc ^ (prow & 7))) << 4);

#define ISSUE_STAGE(kt, s)                                              \
    do {                                                                \
        uint32_t dA = sbase + (s) * STG + so;                           \
        uint32_t dB = dA + A_STG;                                       \
        const __nv_bfloat16* pa = gA + (kt) * BK;                       \
        const __nv_bfloat16* pb = gB + (kt) * BK;                       \
        _Pragma("unroll")                                               \
        for (int i = 0; i < 8; i++)                                     \
            CPASYNC16(dA + 4096u * i, pa + (size_t)32 * i * R);         \
        _Pragma("unroll")                                               \
        for (int i = 0; i < 4; i++)                                     \
            CPASYNC16(dB + 4096u * i, pb + (size_t)32 * i * R);         \
    } while (0)

    // ---- consumer addressing: warp (wid>>1) along M, (wid&1) along N ----
    const int wm = (wid >> 1) * 64;
    const int wn = (wid & 1) * 64;
    const int l15 = lane & 15;
    const int lhi = lane >> 4;
    const int l7  = lane & 7;

    uint32_t aoff[4], boff[4];
    #pragma unroll
    for (int fm = 0; fm < 4; fm++) aoff[fm] = (uint32_t)(wm + fm * 16 + l15) * 128;
    #pragma unroll
    for (int nb = 0; nb < 4; nb++)  boff[nb] = (uint32_t)(wn + nb * 16 + l15) * 128 + A_STG;

    float c[4][8][4];
    #pragma unroll
    for (int fm = 0; fm < 4; fm++)
        #pragma unroll
        for (int nf = 0; nf < 8; nf++)
            #pragma unroll
            for (int v = 0; v < 4; v++) c[fm][nf][v] = 0.f;

    ISSUE_STAGE(0, 0); CPASYNC_COMMIT();
    ISSUE_STAGE(1, 1); CPASYNC_COMMIT();
    ISSUE_STAGE(2, 2); CPASYNC_COMMIT();

    for (int kt = 0; kt < NKC; kt++) {
        const int s = kt & (NSTG - 1);
        CPASYNC_WAIT2();
        __syncthreads();   // all warps done reading stage (kt-1)&3 before it is rewritten

        if (kt + 3 < NKC) { ISSUE_STAGE(kt + 3, (kt + 3) & (NSTG - 1)); }
        CPASYNC_COMMIT();

        const uint32_t st = sbase + s * STG;
        #pragma unroll
        for (int kk = 0; kk < 4; kk++) {
            const uint32_t sw = (uint32_t)(((kk * 2 + lhi) ^ l7)) << 4;

            uint32_t a[4][4], bq[4][4];
            #pragma unroll
            for (int fm = 0; fm < 4; fm++)
                LDSM_X4(a[fm][0], a[fm][1], a[fm][2], a[fm][3], st + aoff[fm] + sw);
            #pragma unroll
            for (int nb = 0; nb < 4; nb++)
                LDSM_X4(bq[nb][0], bq[nb][1], bq[nb][2], bq[nb][3], st + boff[nb] + sw);

            #pragma unroll
            for (int fm = 0; fm < 4; fm++)
                #pragma unroll
                for (int nf = 0; nf < 8; nf++) {
                    const int nb = nf >> 1, od = nf & 1;
                    MMA_BF16(c[fm][nf], a[fm][0], a[fm][1], a[fm][2], a[fm][3],
                             bq[nb][od], bq[nb][od + 2]);
                }
        }
    }

    // ---- epilogue ----
    const int g  = lane >> 2;
    const int t2 = (lane & 3) * 2;
    #pragma unroll
    for (int fm = 0; fm < 4; fm++) {
        float* p0 = C + (size_t)(bm + wm + fm * 16 + g) * R + bn + wn + t2;
        #pragma unroll
        for (int nf = 0; nf < 8; nf++) {
            *(float2*)(p0 + nf * 8)         = make_float2(c[fm][nf][0], c[fm][nf][1]);
            *(float2*)(p0 + 8 * R + nf * 8) = make_float2(c[fm][nf][2], c[fm][nf][3]);
        }
    }
#undef ISSUE_STAGE
}

// ---------------- elementwise log-prob (fast-math, float4) ----------------
#define LOG2PI 1.8378770664093454836f

__device__ __forceinline__ float lp_all(
    float s, float e, float i, float tt,
    float se, float ei, float it, float iu, float tr, float td,
    float det, float rec, float con, float ai, float inv_an,
    float dE, float dI, float dT)
{
    float z   = con * ai * inv_an;
    float pSE = 1.f - __expf(-z);
    float mS  = s * pSE;
    float covS = mS * (1.f - pSE);
    float dS  = se - mS;
    float quadS = __fdividef(dS * dS, covS);

    float mE  = e * dE;
    float covE = mE * (1.f - dE);
    float dEe = ei - mE;
    float quadE = __fdividef(dEe * dEe, covE);

    float l1 = __logf(covS * covE);

    float p1 = det * dI, p2 = (1.f - det) * dI;
    float m1 = i * p1, m2 = i * p2;
    float d1 = it - m1, d2 = iu - m2;
    float c11 = m1 * (1.f - p1);
    float c22 = m2 * (1.f - p2);
    float c12 = -(m1 * p2);
    float detI = i * m1 * p2 * (1.f - p1 - p2);
    float quadI = __fdividef(d1 * d1 * c22 - 2.f * d1 * d2 * c12 + d2 * d2 * c11, detI);

    float q1 = rec * dT, q2 = (1.f - rec) * dT;
    float n1 = tt * q1, n2 = tt * q2;
    float e1 = tr - n1, e2 = td - n2;
    float b11 = n1 * (1.f - q1);
    float b22 = n2 * (1.f - q2);
    float b12 = -(n1 * q2);
    float detT = tt * n1 * q2 * (1.f - q1 - q2);
    float quadT = __fdividef(e1 * e1 * b22 - 2.f * e1 * e2 * b12 + e2 * e2 * b11, detT);

    float l2 = __logf(detI * detT);

    return -0.5f * (6.f * LOG2PI + l1 + l2 + quadS + quadE + quadI + quadT);
}

__global__ void __launch_bounds__(128) elem_kernel(
    const float* __restrict__ S,   const float* __restrict__ E,
    const float* __restrict__ I,   const float* __restrict__ T,
    const float* __restrict__ S_E, const float* __restrict__ E_I,
    const float* __restrict__ I_T, const float* __restrict__ I_U,
    const float* __restrict__ T_R, const float* __restrict__ T_D,
    const float* __restrict__ detr, const float* __restrict__ recr,
    const float* __restrict__ cont,
    const float* __restrict__ pdE, const float* __restrict__ pdI,
    const float* __restrict__ pdT)
{
    const int r  = (blockIdx.x * blockDim.x + threadIdx.x) * 4;
    const int t0 = blockIdx.y * TCHUNK;
    int t1 = t0 + TCHUNK; if (t1 > TT) t1 = TT;

    float4 an = *(const float4*)&g_AN[r];
    float inv0 = __fdividef(1.f, an.x), inv1 = __fdividef(1.f, an.y);
    float inv2 = __fdividef(1.f, an.z), inv3 = __fdividef(1.f, an.w);
    float dE = __fdividef(1.f, 1.f + __expf(-pdE[0]));
    float dI = __fdividef(1.f, 1.f + __expf(-pdI[0]));
    float dT = __fdividef(1.f, 1.f + __expf(-pdT[0]));

    float a0 = 0.f, a1 = 0.f, a2 = 0.f, a3 = 0.f;
    for (int t = t0; t < t1; t++) {
        size_t idx = (size_t)t * R + r;
        float4 vS  = *(const float4*)(S + idx);
        float4 vE  = *(const float4*)(E + idx);
        float4 vI  = *(const float4*)(I + idx);
        float4 vT  = *(const float4*)(T + idx);
        float4 vse = *(const float4*)(S_E + idx);
        float4 vei = *(const float4*)(E_I + idx);
        float4 vit = *(const float4*)(I_T + idx);
        float4 viu = *(const float4*)(I_U + idx);
        float4 vtr = *(const float4*)(T_R + idx);
        float4 vtd = *(const float4*)(T_D + idx);
        float4 vdt = *(const float4*)(detr + idx);
        float4 vrc = *(const float4*)(recr + idx);
        float4 vcn = *(const float4*)(cont + idx);
        float4 vai = *(const float4*)(g_AI + idx);

        a0 += lp_all(vS.x, vE.x, vI.x, vT.x, vse.x, vei.x, vit.x, viu.x, vtr.x, vtd.x,
                     vdt.x, vrc.x, vcn.x, vai.x, inv0, dE, dI, dT);
        a1 += lp_all(vS.y, vE.y, vI.y, vT.y, vse.y, vei.y, vit.y, viu.y, vtr.y, vtd.y,
                     vdt.y, vrc.y, vcn.y, vai.y, inv1, dE, dI, dT);
        a2 += lp_all(vS.z, vE.z, vI.z, vT.z, vse.z, vei.z, vit.z, viu.z, vtr.z, vtd.z,
                     vdt.z, vrc.z, vcn.z, vai.z, inv2, dE, dI, dT);
        a3 += lp_all(vS.w, vE.w, vI.w, vT.w, vse.w, vei.w, vit.w, viu.w, vtr.w, vtd.w,
                     vdt.w, vrc.w, vcn.w, vai.w, inv3, dE, dI, dT);
    }
    *(float4*)&g_partial[(size_t)blockIdx.y * R + r] = make_float4(a0, a1, a2, a3);
}

// ---------------- final deterministic reduce over chunks ----------------
__global__ void reduce_kernel(float* __restrict__ out) {
    int r = blockIdx.x * blockDim.x + threadIdx.x;
    float s = 0.f;
    #pragma unroll
    for (int c = 0; c < NCHUNKS; c++) s += g_partial[c * R + r];
    out[r] = s;
}

// ---------------- launch ----------------
extern "C" void kernel_launch(void* const* d_in, const int* in_sizes, int n_in,
                              void* d_out, int out_size) {
    const float* S    = (const float*)d_in[0];
    const float* E    = (const float*)d_in[1];
    const float* I    = (const float*)d_in[2];
    const float* T    = (const float*)d_in[3];
    const float* N    = (const float*)d_in[4];
    const float* S_E  = (const float*)d_in[5];
    const float* E_I  = (const float*)d_in[6];
    const float* I_T  = (const float*)d_in[7];
    const float* I_U  = (const float*)d_in[8];
    const float* T_R  = (const float*)d_in[9];
    const float* T_D  = (const float*)d_in[10];
    const float* adj  = (const float*)d_in[11];
    const float* ldE  = (const float*)d_in[12];
    const float* ldI  = (const float*)d_in[13];
    const float* ldT  = (const float*)d_in[14];
    const float* detr = (const float*)d_in[15];
    const float* recr = (const float*)d_in[16];
    const float* cont = (const float*)d_in[17];
    float* out = (float*)d_out;

    float* AI;             cudaGetSymbolAddress((void**)&AI, g_AI);
    __nv_bfloat16* Ib;     cudaGetSymbolAddress((void**)&Ib, g_Ib);
    __nv_bfloat16* ADJb;   cudaGetSymbolAddress((void**)&ADJb, g_ADJb);

    cudaFuncSetAttribute(gemm_mma, cudaFuncAttributeMaxDynamicSharedMemorySize, GEMM_SMEM);

    // 0) fused adj: bf16 convert + AN = adj @ N;  I: bf16 convert
    cvt_adj_an<<<R, 128>>>(adj, N, ADJb);
    cvt_kernel<<<512, 256>>>(I, Ib, (int)((size_t)D * R / 8));

    // 1) AI = I @ adj^T via mma.sync bf16 (single wave: 128 CTAs)
    gemm_mma<<<dim3(R / BN, D / BM), 256, GEMM_SMEM>>>(Ib, ADJb, AI);

    // 2) elementwise log-probs (fast-math, float4), partial sums over t chunks
    elem_kernel<<<dim3(R / 512, NCHUNKS), 128>>>(
        S, E, I, T, S_E, E_I, I_T, I_U, T_R, T_D,
        detr, recr, cont, ldE, ldI, ldT);

    // 3) deterministic final reduce
    reduce_kernel<<<R / 128, 128>>>(out);
}